// round 15
// baseline (speedup 1.0000x reference)
#include <cuda_runtime.h>

#define NTH   640
#define NWARP (NTH / 32)
#define CAPV  16384
#define CH    256
#define ENT   6
#define ELCAP 2048
#define SENT  (-1e38f)
#define NEGV  (-1e30f)
#define NFMAX 6000

// shared-memory float offsets
#define OFF_RAW0  0              // 16392: guard [0..3], V0 = +4
#define OFF_RAW1  16392          // 16392: guard [0..3], V1 = +4
#define OFF_LT    32784          // 4096
#define OFF_DENS  36880          // 18000 (rv/ri overlay at end)
#define OFF_CANDM 54880          // 4*256: cand_m at m*256 + b*64 + i
#define OFF_TBUF  55904          // 4*256: T at task*4 + m  (16B-aligned)
#define OFF_PLSM  56928          // 256
#define OFF_FMASK 57184          // 512 uints (first-state bitmask)
#define OFF_MISC  57696          // 96: [0]=tot, [8..27]=wtot, [32..95]=band
#define SM_FLOATS 57792          // 231,168 B

__device__ float g_hist[NFMAX * CH];   // v_t[prev_last] history for backtrace

typedef unsigned long long u64;
__device__ __forceinline__ u64 pk2(float a, float b) {
    u64 r; asm("mov.b64 %0,{%1,%2};" : "=l"(r) : "f"(a), "f"(b)); return r;
}
__device__ __forceinline__ void upk2(u64 p, float& a, float& b) {
    asm("mov.b64 {%0,%1},%2;" : "=f"(a), "=f"(b) : "l"(p));
}
__device__ __forceinline__ u64 padd2(u64 a, u64 b) {
    u64 r; asm("add.rn.f32x2 %0, %1, %2;" : "=l"(r) : "l"(a), "l"(b)); return r;
}

// classify state s for the fused-4 update. Returns 1 + meta/start if exceptional.
__device__ __forceinline__ int classify(int s, const int* __restrict__ ptr,
                                        const unsigned* fmask, const int* fof0,
                                        int* meta, int* start)
{
    int r = -1;
    #pragma unroll
    for (int k = 0; k < 4; k++) {
        int x = s - k;
        if (r < 0 && x >= 0 && ((fmask[x >> 5] >> (x & 31)) & 1u)) r = k;
    }
    if (r >= 0) {   // within 3 of a first state f = s-r
        int f = s - r, j = fof0[f], m0 = 3 - r;
        unsigned codes = 0;
        #pragma unroll
        for (int m = 0; m < 4; m++) {
            unsigned c = (m < m0) ? 3u : (unsigned)__ldg(ptr + (f + (m - m0)));
            codes |= c << (2 * m);
        }
        *meta  = s | (1 << 14) | ((int)codes << 16);
        *start = j * 4 + m0;             // Tbuf index: task*4 + m0
        return 1;
    }
    unsigned codes = 0; int nz = 0;
    #pragma unroll
    for (int m = 0; m < 4; m++) {
        unsigned c = (unsigned)__ldg(ptr + (s - 3 + m));
        codes |= c << (2 * m);
        nz |= (c != 0u);
    }
    if (!nz) return 0;                   // clean dense state
    *meta  = s | ((int)codes << 16);
    *start = s - 4;                      // Vc index
    return 1;
}

__global__ void __launch_bounds__(NTH, 1)
dbn_kernel(const float* __restrict__ acts,
           const float* __restrict__ log_trans,
           const int*   __restrict__ prev_last,
           const int*   __restrict__ first_states,
           const int*   __restrict__ pointer,
           float*       __restrict__ out,
           int S, int T, int NF, int out_size)
{
    extern __shared__ float smf[];
    float* V0    = smf + OFF_RAW0 + 4;
    float* V1    = smf + OFF_RAW1 + 4;
    float* lt    = smf + OFF_LT;
    float* dens  = smf + OFF_DENS;
    float* candm = smf + OFF_CANDM;
    float* Tsm   = smf + OFF_TBUF;
    int*   plsm  = (int*)(smf + OFF_PLSM);
    unsigned* fmask = (unsigned*)(smf + OFF_FMASK);
    int*   misc  = (int*)(smf + OFF_MISC);
    int*   band  = misc + 32;

    const int tid  = threadIdx.x;
    const int lane = tid & 31;
    const int wid  = tid >> 5;
    const int NT4  = 4 * T;

    // dense role: warps 15..19 own ALL live blocks (states < S)
    const int NBLK = (S + 127) >> 7;              // ceil(S/128)
    int my_nb = 0, my_b0 = 0;
    if (wid >= 15) {
        int dw = wid - 15;
        int q = NBLK / 5, r = NBLK % 5;
        my_nb = q + (dw < r ? 1 : 0);
        my_b0 = dw * q + (dw < r ? dw : r);
    }

    // ---------------- setup: tables ----------------
    for (int i = tid; i < T * T; i += NTH) lt[i] = log_trans[i];
    if (tid < NT4) plsm[tid] = prev_last[tid];
    for (int i = tid; i < 512; i += NTH) fmask[i] = 0u;
    for (int i = tid; i < 1024; i += NTH) candm[i] = 0.f;   // pads stay 0
    __syncthreads();

    int* fof0 = (int*)(smf + OFF_RAW0);      // setup overlay on V0 region
    if (tid < NT4) {
        int fs = first_states[tid];
        atomicOr(&fmask[fs >> 5], 1u << (fs & 31));
        fof0[fs] = tid;
    }
    __syncthreads();

    // ---------------- setup: exception entries (deterministic scan) ----------------
    int cnt = 0;
    for (int k = 0; k < 32; k++) {
        int s = (tid << 5) + k;
        if (s < S) { int mt, stx; cnt += classify(s, pointer, fmask, fof0, &mt, &stx); }
    }
    int inc = cnt;
    #pragma unroll
    for (int off = 1; off < 32; off <<= 1) {
        int n = __shfl_up_sync(0xffffffffu, inc, off);
        if (lane >= off) inc += n;
    }
    int* wtot = misc + 8;
    if (lane == 31) wtot[wid] = inc;
    __syncthreads();
    if (tid == 0) {
        int acc = 0;
        for (int w = 0; w < NWARP; w++) { int tw = wtot[w]; wtot[w] = acc; acc += tw; }
        misc[0] = acc;
    }
    __syncthreads();
    int base = wtot[wid] + inc - cnt;
    int* ex = (int*)(smf + OFF_RAW1);        // setup overlay on V1 region
    int* ey = ex + ELCAP;
    for (int k = 0; k < 32; k++) {
        int s = (tid << 5) + k;
        if (s < S) {
            int mt, stx;
            if (classify(s, pointer, fmask, fof0, &mt, &stx)) {
                if (base < ELCAP) { ex[base] = mt; ey[base] = stx; }
                base++;
            }
        }
    }
    // band per column j: contiguous finite range of lt[:,j]; 48-wide aligned
    if (tid < T) {
        int lo = 0;
        for (int i = 0; i < T; i++) if (lt[i * T + tid] > -1e28f) { lo = i; break; }
        int lo4 = lo & ~3;
        if (lo4 > 16) lo4 = 16;
        band[tid] = lo4;
    }
    __syncthreads();
    int nent = min(misc[0], ELCAP);
    int ems[ENT], eys[ENT];
    {
        int eb = tid * ENT;                  // exceptions live on LOW tids
        #pragma unroll
        for (int e = 0; e < ENT; e++) {
            int ix = eb + e;
            if (ix < nent) { ems[e] = ex[ix]; eys[e] = ey[ix]; }
            else           { ems[e] = -1;     eys[e] = 0; }
        }
    }
    __syncthreads();                         // overlays dead; V0/V1 free

    // ---------------- setup: V0, guards, densities ----------------
    {
        float v0i = -logf((float)S);
        for (int s = tid; s < CAPV; s += NTH) V0[s] = v0i;
        if (tid < 4) { smf[OFF_RAW0 + tid] = NEGV; smf[OFF_RAW1 + tid] = NEGV; }
        for (int f = tid; f < NF; f += NTH) {
            float ab = acts[2 * f], ad = acts[2 * f + 1];
            dens[3 * f + 0] = logf((1.f - ab - ad) * (1.f / 15.f));
            dens[3 * f + 1] = logf(ab);
            dens[3 * f + 2] = logf(ad);
        }
    }

    // transition roles: 2 threads per task; band-compressed lt window in regs
    const bool isA  = (tid < 2 * NT4);
    const int  task  = tid >> 1;
    const int  cpart = tid & 1;
    int a_b = 0, a_faddr = 0, a_fc = 1;
    if (isA) {
        a_b = task / T;
        a_faddr = __ldg(first_states + task);
        a_fc = __ldg(pointer + a_faddr);     // 2 for beat0, else 1
    }
    __syncthreads();                         // lt/band ready; V0/dens ready

    float ltreg[24];
    int cb4 = 0;
    const bool skip = !isA;
    if (isA) {
        int a_j = task - a_b * T;
        int lo4 = band[a_j];
        cb4 = (a_b << 4) + (lo4 >> 2) + cpart * 6;     // float4 units
        #pragma unroll
        for (int q = 0; q < 24; q++) {
            int i = lo4 + cpart * 24 + q;
            ltreg[q] = (i < T) ? lt[i * T + a_j] : SENT;
        }
    } else {
        #pragma unroll
        for (int q = 0; q < 24; q++) ltreg[q] = SENT;
    }

    // staging role: tid in [400, 400+NT4)
    const int st = tid - 400;
    const bool stOK = (st >= 0 && st < NT4);
    int my_pl = 0, coff = 0;
    if (stOK) { my_pl = plsm[st]; int b = st / T; coff = (b << 6) + (st - b * T); }

    const int dL4 = lane << 2;

    int rem = NF & 3;
    int NFf = NF - rem;

    // pre-stage cand_0..3 from V0 (frames 0..3)
    if (NFf > 0 && stOK) {
        float e0 = dens[0], e1 = dens[3], e2 = dens[6];
        float c0 = V0[my_pl];
        float c1 = V0[my_pl - 1] + e0;
        float c2 = (V0[my_pl - 2] + e0) + e1;
        float c3 = ((V0[my_pl - 3] + e0) + e1) + e2;
        candm[coff] = c0; candm[256 + coff] = c1;
        candm[512 + coff] = c2; candm[768 + coff] = c3;
        g_hist[0 * CH + st] = c0; g_hist[1 * CH + st] = c1;
        g_hist[2 * CH + st] = c2; g_hist[3 * CH + st] = c3;
    }

    int cur = 0;

    // ---------------- fused-4 forward loop: 2 barriers / 4 frames ----------------
    for (int t = 0; t < NFf; t += 4) {
        float* Vc = cur ? V1 : V0;
        float* Vn = cur ? V0 : V1;
        __syncthreads();   // cand staged + exceptions applied to Vc

        float dd[4][3];
        #pragma unroll
        for (int m = 0; m < 4; m++) {
            dd[m][0] = dens[3 * (t + m) + 0];
            dd[m][1] = dens[3 * (t + m) + 1];
            dd[m][2] = dens[3 * (t + m) + 2];
        }

        // dense (warps 15-19 only): v_{t+4}[s] = v_t[s-4] + d0 chain, f32x2
        if (my_nb) {
            u64 D0 = pk2(dd[0][0], dd[0][0]);
            u64 D1 = pk2(dd[1][0], dd[1][0]);
            u64 D2 = pk2(dd[2][0], dd[2][0]);
            u64 D3 = pk2(dd[3][0], dd[3][0]);
            for (int g = 0; g < my_nb; g++) {
                int idx = ((my_b0 + g) << 7) + dL4;
                float4 A = *(const float4*)(Vc + idx - 4);
                u64 p0 = pk2(A.x, A.y), p1 = pk2(A.z, A.w);
                p0 = padd2(p0, D0); p1 = padd2(p1, D0);
                p0 = padd2(p0, D1); p1 = padd2(p1, D1);
                p0 = padd2(p0, D2); p1 = padd2(p1, D2);
                p0 = padd2(p0, D3); p1 = padd2(p1, D3);
                float4 o; upk2(p0, o.x, o.y); upk2(p1, o.z, o.w);
                *(float4*)(Vn + idx) = o;
            }
        }

        // transitions (warps 0-14): T[task*4+m] = max_i cand_m[i] + lt[i][j]
        if (!skip) {
            float tm[4];
            #pragma unroll
            for (int m = 0; m < 4; m++) {
                const float4* c4 = (const float4*)(candm + (m << 8)) + cb4;
                float a0 = SENT, a1 = SENT, a2 = SENT, a3 = SENT;
                #pragma unroll
                for (int q = 0; q < 6; q++) {
                    float4 cv = c4[q];
                    a0 = fmaxf(a0, cv.x + ltreg[4 * q + 0]);
                    a1 = fmaxf(a1, cv.y + ltreg[4 * q + 1]);
                    a2 = fmaxf(a2, cv.z + ltreg[4 * q + 2]);
                    a3 = fmaxf(a3, cv.w + ltreg[4 * q + 3]);
                }
                float am = fmaxf(fmaxf(a0, a1), fmaxf(a2, a3));
                float o = __shfl_down_sync(0xffffffffu, am, 1);
                tm[m] = fmaxf(am, o);
            }
            if (cpart == 0) {
                float4 tv; tv.x = tm[0]; tv.y = tm[1]; tv.z = tm[2]; tv.w = tm[3];
                *(float4*)(Tsm + task * 4) = tv;
            }
        }

        __syncthreads();   // Tbuf + dense Vn visible

        // exceptions (low tids): unified start + 4 slot-coded density adds
        #pragma unroll
        for (int e = 0; e < ENT; e++) {
            int me = ems[e];
            if (me >= 0) {
                int s = me & 0x3FFF;
                int kindA = (me >> 14) & 1;
                unsigned codes = ((unsigned)me) >> 16;
                float val = kindA ? Tsm[eys[e]] : Vc[eys[e]];
                #pragma unroll
                for (int m = 0; m < 4; m++) {
                    unsigned c = (codes >> (2 * m)) & 3u;
                    float add = (c == 0u) ? dd[m][0]
                              : (c == 1u) ? dd[m][1]
                              : (c == 2u) ? dd[m][2] : 0.f;
                    val += add;
                }
                Vn[s] = val;
            }
        }

        // staging (tids 400-639): next step's cand from Vn (dense-written slots)
        if (stOK && t + 4 < NFf) {
            float e0 = dens[3 * (t + 4)], e1 = dens[3 * (t + 5)], e2 = dens[3 * (t + 6)];
            float c0 = Vn[my_pl];
            float c1 = Vn[my_pl - 1] + e0;
            float c2 = (Vn[my_pl - 2] + e0) + e1;
            float c3 = ((Vn[my_pl - 3] + e0) + e1) + e2;
            candm[coff] = c0; candm[256 + coff] = c1;
            candm[512 + coff] = c2; candm[768 + coff] = c3;
            int hb = (t + 4) * CH + st;
            g_hist[hb] = c0; g_hist[hb + CH] = c1;
            g_hist[hb + 2 * CH] = c2; g_hist[hb + 3 * CH] = c3;
        }
        cur ^= 1;
    }

    // ---------------- tail frames (NF % 4; normally 0) ----------------
    for (int t = NFf; t < NF; t++) {
        float* Vc = cur ? V1 : V0;
        float* Vn = cur ? V0 : V1;
        __syncthreads();
        if (stOK) { float cv = Vc[my_pl]; candm[coff] = cv; g_hist[t * CH + st] = cv; }
        __syncthreads();
        float d0 = dens[3 * t], d1 = dens[3 * t + 1], d2 = dens[3 * t + 2];
        for (int g = wid; g < NBLK; g += NWARP) {
            int idx = (g << 7) + dL4;
            float4 A = *(const float4*)(Vc + idx);
            float pm = Vc[idx - 1];
            float4 o; o.x = pm + d0; o.y = A.x + d0; o.z = A.y + d0; o.w = A.z + d0;
            *(float4*)(Vn + idx) = o;
        }
        float acc = SENT;
        if (!skip) {
            const float4* c4 = (const float4*)candm + cb4;
            #pragma unroll
            for (int q = 0; q < 6; q++) {
                float4 cv = c4[q];
                acc = fmaxf(acc, cv.x + ltreg[4 * q + 0]);
                acc = fmaxf(acc, cv.y + ltreg[4 * q + 1]);
                acc = fmaxf(acc, cv.z + ltreg[4 * q + 2]);
                acc = fmaxf(acc, cv.w + ltreg[4 * q + 3]);
            }
        }
        float oth = __shfl_down_sync(0xffffffffu, acc, 1);
        __syncthreads();
        if (isA && cpart == 0) Vn[a_faddr] = fmaxf(acc, oth) + (a_fc == 2 ? d2 : d1);
        for (int s = tid; s < S; s += NTH) {
            int c = __ldg(pointer + s);
            if (c != 0 && !((fmask[s >> 5] >> (s & 31)) & 1u))
                Vn[s] = Vc[s - 1] + (c == 2 ? d2 : d1);
        }
        cur ^= 1;
    }
    __syncthreads();

    // ---------------- final argmax + backtrace ----------------
    float* Vf = cur ? V1 : V0;
    float* Vd = cur ? V0 : V1;
    float* rv = dens;
    int*   ri = (int*)(dens + NTH);
    int*   fof = (int*)Vd;
    if (isA && cpart == 0) fof[a_faddr] = task;
    {
        float bv = SENT; int bi = 0x7fffffff;
        for (int s = tid; s < S; s += NTH) {
            float x = Vf[s];
            if (x > bv) { bv = x; bi = s; }
        }
        rv[tid] = bv; ri[tid] = bi;
    }
    __syncthreads();

    if (wid == 0) {
        float bv = SENT; int bi = 0x7fffffff;
        for (int m = lane; m < NTH; m += 32) {
            float x = rv[m]; int ii = ri[m];
            if (x > bv || (x == bv && ii < bi)) { bv = x; bi = ii; }
        }
        #pragma unroll
        for (int off = 16; off; off >>= 1) {
            float xv = __shfl_down_sync(0xffffffffu, bv, off);
            int   xi = __shfl_down_sync(0xffffffffu, bi, off);
            if (xv > bv || (xv == bv && xi < bi)) { bv = xv; bi = xi; }
        }
        bi = __shfl_sync(0xffffffffu, bi, 0);
        bv = __shfl_sync(0xffffffffu, bv, 0);
        if (lane == 0) {
            if (out_size > NF) out[NF] = bv;   // logp
            out[NF - 1] = (float)bi;           // path[NF-1]
        }

        int s = bi, tt = NF - 1;
        while (tt > 0) {
            bool isf = (fmask[s >> 5] >> (s & 31)) & 1u;
            if (isf) {
                int f = fof[s];
                int b = f / T, j = f - b * T;
                float bvv = SENT; int bii = 0x7fffffff;
                for (int i = lane; i < T; i += 32) {
                    float x = g_hist[tt * CH + b * T + i] + lt[i * T + j];
                    if (x > bvv || (x == bvv && i < bii)) { bvv = x; bii = i; }
                }
                #pragma unroll
                for (int off = 16; off; off >>= 1) {
                    float xv = __shfl_down_sync(0xffffffffu, bvv, off);
                    int   xi = __shfl_down_sync(0xffffffffu, bii, off);
                    if (xv > bvv || (xv == bvv && xi < bii)) { bvv = xv; bii = xi; }
                }
                bii = __shfl_sync(0xffffffffu, bii, 0);
                int p = plsm[b * T + bii];
                if (lane == 0) out[tt - 1] = (float)p;
                s = p; tt -= 1;
            } else {
                int ss = s - 1 - lane;
                bool ef = (ss < 0) ? true : (((fmask[ss >> 5] >> (ss & 31)) & 1u) != 0);
                unsigned flags = __ballot_sync(0xffffffffu, ef);
                int cnt2 = flags ? __ffs(flags) : 32;
                cnt2 = min(cnt2, tt);
                if (lane < cnt2) out[tt - 1 - lane] = (float)(s - 1 - lane);
                s -= cnt2; tt -= cnt2;
            }
        }
    }
}

extern "C" void kernel_launch(void* const* d_in, const int* in_sizes, int n_in,
                              void* d_out, int out_size)
{
    const float* acts = (const float*)d_in[0];
    const float* ltg  = (const float*)d_in[1];
    const int*   pl   = (const int*)d_in[2];
    const int*   fs   = (const int*)d_in[3];
    const int*   ptr  = (const int*)d_in[4];

    int NF = in_sizes[0] / 2;
    int T  = in_sizes[2] / 4;
    int S  = in_sizes[4];
    if (NF > NFMAX) NF = NFMAX;

    size_t smem = (size_t)SM_FLOATS * sizeof(float);
    static bool attr_set = false;
    if (!attr_set) {
        cudaFuncSetAttribute(dbn_kernel,
                             cudaFuncAttributeMaxDynamicSharedMemorySize, (int)smem);
        attr_set = true;
    }
    dbn_kernel<<<1, NTH, smem>>>(acts, ltg, pl, fs, ptr,
                                 (float*)d_out, S, T, NF, out_size);
}

// round 16
// speedup vs baseline: 1.4128x; 1.4128x over previous
#include <cuda_runtime.h>

#define NTH   512
#define CAPV  16384
#define CH    256
#define ENT   4
#define ELCAP 2048
#define SENT  (-1e38f)
#define NEGV  (-1e30f)
#define NFMAX 6000

// shared-memory float offsets
#define OFF_RAW0  0              // 16392: guard [0..3], V0 = +4
#define OFF_RAW1  16392          // 16392: guard [0..3], V1 = +4
#define OFF_LT    32784          // 4096
#define OFF_DENS  36880          // 18000 (rv/ri overlay at end)
#define OFF_CANDM 54880          // 4*256: cand_m at m*256 + b*64 + i
#define OFF_TBUF  55904          // 4*256: T at task*4 + m  (16B-aligned)
#define OFF_PLSM  56928          // 256
#define OFF_FMASK 57184          // 512 uints (first-state bitmask)
#define OFF_MISC  57696          // 96: [0]=tot, [8..23]=wtot, [32..95]=band
#define SM_FLOATS 57792          // 231,168 B

__device__ float g_hist[NFMAX * CH];   // v_t[prev_last] history for backtrace

typedef unsigned long long u64;
__device__ __forceinline__ u64 pk2(float a, float b) {
    u64 r; asm("mov.b64 %0,{%1,%2};" : "=l"(r) : "f"(a), "f"(b)); return r;
}
__device__ __forceinline__ void upk2(u64 p, float& a, float& b) {
    asm("mov.b64 {%0,%1},%2;" : "=f"(a), "=f"(b) : "l"(p));
}
__device__ __forceinline__ u64 padd2(u64 a, u64 b) {
    u64 r; asm("add.rn.f32x2 %0, %1, %2;" : "=l"(r) : "l"(a), "l"(b)); return r;
}

// classify state s for the fused-4 update. Returns 1 + meta/start if exceptional.
__device__ __forceinline__ int classify(int s, const int* __restrict__ ptr,
                                        const unsigned* fmask, const int* fof0,
                                        int* meta, int* start)
{
    int r = -1;
    #pragma unroll
    for (int k = 0; k < 4; k++) {
        int x = s - k;
        if (r < 0 && x >= 0 && ((fmask[x >> 5] >> (x & 31)) & 1u)) r = k;
    }
    if (r >= 0) {   // within 3 of a first state f = s-r
        int f = s - r, j = fof0[f], m0 = 3 - r;
        unsigned codes = 0;
        #pragma unroll
        for (int m = 0; m < 4; m++) {
            unsigned c = (m < m0) ? 3u : (unsigned)__ldg(ptr + (f + (m - m0)));
            codes |= c << (2 * m);
        }
        *meta  = s | (1 << 14) | ((int)codes << 16);
        *start = j * 4 + m0;             // Tbuf index: task*4 + m0
        return 1;
    }
    unsigned codes = 0; int nz = 0;
    #pragma unroll
    for (int m = 0; m < 4; m++) {
        unsigned c = (unsigned)__ldg(ptr + (s - 3 + m));
        codes |= c << (2 * m);
        nz |= (c != 0u);
    }
    if (!nz) return 0;                   // clean dense state
    *meta  = s | ((int)codes << 16);
    *start = s - 4;                      // Vc index
    return 1;
}

__global__ void __launch_bounds__(NTH, 1)
dbn_kernel(const float* __restrict__ acts,
           const float* __restrict__ log_trans,
           const int*   __restrict__ prev_last,
           const int*   __restrict__ first_states,
           const int*   __restrict__ pointer,
           float*       __restrict__ out,
           int S, int T, int NF, int out_size)
{
    extern __shared__ float smf[];
    float* V0    = smf + OFF_RAW0 + 4;
    float* V1    = smf + OFF_RAW1 + 4;
    float* lt    = smf + OFF_LT;
    float* dens  = smf + OFF_DENS;
    float* candm = smf + OFF_CANDM;
    float* Tsm   = smf + OFF_TBUF;
    int*   plsm  = (int*)(smf + OFF_PLSM);
    unsigned* fmask = (unsigned*)(smf + OFF_FMASK);
    int*   misc  = (int*)(smf + OFF_MISC);
    int*   band  = misc + 32;

    const int tid  = threadIdx.x;
    const int lane = tid & 31;
    const int wid  = tid >> 5;
    const int NT4  = 4 * T;

    // live dense blocks: only states < S matter. 113 blocks of 128 for S=14344.
    const int NBLK = (S + 127) >> 7;              // ceil(S/128)
    const int nb_lo = NBLK >> 4;                  // blocks for warps 0..14
    const int my_nb = (wid < 15) ? nb_lo : (NBLK - 15 * nb_lo);
    const int my_b0 = (wid < 15) ? wid * nb_lo : 15 * nb_lo;

    // ---------------- setup: tables ----------------
    for (int i = tid; i < T * T; i += NTH) lt[i] = log_trans[i];
    if (tid < NT4) plsm[tid] = prev_last[tid];
    for (int i = tid; i < 512; i += NTH) fmask[i] = 0u;
    for (int i = tid; i < 1024; i += NTH) candm[i] = 0.f;   // pads stay 0
    __syncthreads();

    int* fof0 = (int*)(smf + OFF_RAW0);      // setup overlay on V0 region
    if (tid < NT4) {
        int fs = first_states[tid];
        atomicOr(&fmask[fs >> 5], 1u << (fs & 31));
        fof0[fs] = tid;
    }
    __syncthreads();

    // ---------------- setup: exception entries (deterministic scan) ----------------
    int cnt = 0;
    for (int k = 0; k < 32; k++) {
        int s = (tid << 5) + k;
        if (s < S) { int mt, stx; cnt += classify(s, pointer, fmask, fof0, &mt, &stx); }
    }
    int inc = cnt;
    #pragma unroll
    for (int off = 1; off < 32; off <<= 1) {
        int n = __shfl_up_sync(0xffffffffu, inc, off);
        if (lane >= off) inc += n;
    }
    int* wtot = misc + 8;
    if (lane == 31) wtot[wid] = inc;
    __syncthreads();
    if (tid == 0) {
        int acc = 0;
        for (int w = 0; w < 16; w++) { int tw = wtot[w]; wtot[w] = acc; acc += tw; }
        misc[0] = acc;
    }
    __syncthreads();
    int base = wtot[wid] + inc - cnt;
    int* ex = (int*)(smf + OFF_RAW1);        // setup overlay on V1 region
    int* ey = ex + ELCAP;
    for (int k = 0; k < 32; k++) {
        int s = (tid << 5) + k;
        if (s < S) {
            int mt, stx;
            if (classify(s, pointer, fmask, fof0, &mt, &stx)) {
                if (base < ELCAP) { ex[base] = mt; ey[base] = stx; }
                base++;
            }
        }
    }
    // band per column j: contiguous finite range of lt[:,j] (≤ ~33 wide).
    // 40-wide aligned window [lo4, lo4+40) provably covers it and stays
    // inside the 64-float cand row (lo4 <= 24).
    if (tid < T) {
        int lo = 0;
        for (int i = 0; i < T; i++) if (lt[i * T + tid] > -1e28f) { lo = i; break; }
        int lo4 = lo & ~3;
        if (lo4 > 24) lo4 = 24;
        band[tid] = lo4;
    }
    __syncthreads();
    int nent = min(misc[0], ELCAP);
    int ems[ENT], eys[ENT];
    {
        int eb = (NTH - 1 - tid) * ENT;      // contiguous chunks, high tids first
        #pragma unroll
        for (int e = 0; e < ENT; e++) {
            int ix = eb + e;
            if (ix >= 0 && ix < nent) { ems[e] = ex[ix]; eys[e] = ey[ix]; }
            else                       { ems[e] = -1;     eys[e] = 0; }
        }
    }
    __syncthreads();                         // overlays dead; V0/V1 free

    // ---------------- setup: V0, guards, densities ----------------
    {
        float v0i = -logf((float)S);
        for (int s = tid; s < CAPV; s += NTH) V0[s] = v0i;
        if (tid < 4) { smf[OFF_RAW0 + tid] = NEGV; smf[OFF_RAW1 + tid] = NEGV; }
        for (int f = tid; f < NF; f += NTH) {
            float ab = acts[2 * f], ad = acts[2 * f + 1];
            dens[3 * f + 0] = logf((1.f - ab - ad) * (1.f / 15.f));
            dens[3 * f + 1] = logf(ab);
            dens[3 * f + 2] = logf(ad);
        }
    }

    // transition roles: 2 threads per task; 40-wide band window in regs
    const bool isA  = (tid < 2 * NT4);
    const int  task  = tid >> 1;
    const int  cpart = tid & 1;
    int a_b = 0, a_faddr = 0, a_fc = 1;
    if (isA) {
        a_b = task / T;
        a_faddr = __ldg(first_states + task);
        a_fc = __ldg(pointer + a_faddr);     // 2 for beat0, else 1
    }
    __syncthreads();                         // lt/band ready; V0/dens ready

    float ltreg[20];
    int cb4 = 0;
    const bool skip = !isA;
    if (isA) {
        int a_j = task - a_b * T;
        int lo4 = band[a_j];
        cb4 = (a_b << 4) + (lo4 >> 2) + cpart * 5;     // float4 units
        #pragma unroll
        for (int q = 0; q < 20; q++) {
            int i = lo4 + cpart * 20 + q;
            ltreg[q] = (i < T) ? lt[i * T + a_j] : SENT;
        }
    } else {
        #pragma unroll
        for (int q = 0; q < 20; q++) ltreg[q] = SENT;
    }

    // staging role: tid in [256, 256+NT4)
    const int st = tid - 256;
    const bool stOK = (st >= 0 && st < NT4);
    int my_pl = 0, coff = 0;
    if (stOK) { my_pl = plsm[st]; int b = st / T; coff = (b << 6) + (st - b * T); }

    const int dw0 = wid << 10;
    const int dL4 = lane << 2;

    int rem = NF & 3;
    int NFf = NF - rem;

    // pre-stage cand_0..3 from V0 (frames 0..3)
    if (NFf > 0 && stOK) {
        float e0 = dens[0], e1 = dens[3], e2 = dens[6];
        float c0 = V0[my_pl];
        float c1 = V0[my_pl - 1] + e0;
        float c2 = (V0[my_pl - 2] + e0) + e1;
        float c3 = ((V0[my_pl - 3] + e0) + e1) + e2;
        candm[coff] = c0; candm[256 + coff] = c1;
        candm[512 + coff] = c2; candm[768 + coff] = c3;
        g_hist[0 * CH + st] = c0; g_hist[1 * CH + st] = c1;
        g_hist[2 * CH + st] = c2; g_hist[3 * CH + st] = c3;
    }

    int cur = 0;

    // ---------------- fused-4 forward loop: 2 barriers / 4 frames ----------------
    for (int t = 0; t < NFf; t += 4) {
        float* Vc = cur ? V1 : V0;
        float* Vn = cur ? V0 : V1;
        __syncthreads();   // cand staged + exceptions applied to Vc

        float dd[4][3];
        #pragma unroll
        for (int m = 0; m < 4; m++) {
            dd[m][0] = dens[3 * (t + m) + 0];
            dd[m][1] = dens[3 * (t + m) + 1];
            dd[m][2] = dens[3 * (t + m) + 2];
        }
        u64 D0 = pk2(dd[0][0], dd[0][0]);
        u64 D1 = pk2(dd[1][0], dd[1][0]);
        u64 D2 = pk2(dd[2][0], dd[2][0]);
        u64 D3 = pk2(dd[3][0], dd[3][0]);

        // dense: v_{t+4}[s] = v_t[s-4] + d0 chain, packed f32x2.
        // Only live blocks (states < S): warps 0-14 take nb_lo, warp 15 the rest.
        for (int g = 0; g < my_nb; g++) {
            int idx = ((my_b0 + g) << 7) + dL4;
            float4 A = *(const float4*)(Vc + idx - 4);
            u64 p0 = pk2(A.x, A.y), p1 = pk2(A.z, A.w);
            p0 = padd2(p0, D0); p1 = padd2(p1, D0);
            p0 = padd2(p0, D1); p1 = padd2(p1, D1);
            p0 = padd2(p0, D2); p1 = padd2(p1, D2);
            p0 = padd2(p0, D3); p1 = padd2(p1, D3);
            float4 o; upk2(p0, o.x, o.y); upk2(p1, o.z, o.w);
            *(float4*)(Vn + idx) = o;
        }

        // transitions: T[task*4+m] = max_i cand_m[i] + lt[i][j], 40-wide band
        float tm[4];
        #pragma unroll
        for (int m = 0; m < 4; m++) {
            float am = SENT;
            if (!skip) {
                const float4* c4 = (const float4*)(candm + (m << 8)) + cb4;
                float a0 = SENT, a1 = SENT, a2 = SENT, a3 = SENT;
                #pragma unroll
                for (int q = 0; q < 5; q++) {
                    float4 cv = c4[q];
                    a0 = fmaxf(a0, cv.x + ltreg[4 * q + 0]);
                    a1 = fmaxf(a1, cv.y + ltreg[4 * q + 1]);
                    a2 = fmaxf(a2, cv.z + ltreg[4 * q + 2]);
                    a3 = fmaxf(a3, cv.w + ltreg[4 * q + 3]);
                }
                am = fmaxf(fmaxf(a0, a1), fmaxf(a2, a3));
            }
            float o = __shfl_down_sync(0xffffffffu, am, 1);
            tm[m] = fmaxf(am, o);
        }
        if (isA && cpart == 0) {
            float4 tv; tv.x = tm[0]; tv.y = tm[1]; tv.z = tm[2]; tv.w = tm[3];
            *(float4*)(Tsm + task * 4) = tv;
        }

        __syncthreads();   // Tbuf + dense Vn visible

        // exceptions: unified start + 4 slot-coded density adds
        #pragma unroll
        for (int e = 0; e < ENT; e++) {
            int me = ems[e];
            if (me >= 0) {
                int s = me & 0x3FFF;
                int kindA = (me >> 14) & 1;
                unsigned codes = ((unsigned)me) >> 16;
                float val = kindA ? Tsm[eys[e]] : Vc[eys[e]];
                #pragma unroll
                for (int m = 0; m < 4; m++) {
                    unsigned c = (codes >> (2 * m)) & 3u;
                    float add = (c == 0u) ? dd[m][0]
                              : (c == 1u) ? dd[m][1]
                              : (c == 2u) ? dd[m][2] : 0.f;
                    val += add;
                }
                Vn[s] = val;
            }
        }

        // stage next step's cand from Vn (pl slots are dense-written)
        if (stOK && t + 4 < NFf) {
            float e0 = dens[3 * (t + 4)], e1 = dens[3 * (t + 5)], e2 = dens[3 * (t + 6)];
            float c0 = Vn[my_pl];
            float c1 = Vn[my_pl - 1] + e0;
            float c2 = (Vn[my_pl - 2] + e0) + e1;
            float c3 = ((Vn[my_pl - 3] + e0) + e1) + e2;
            candm[coff] = c0; candm[256 + coff] = c1;
            candm[512 + coff] = c2; candm[768 + coff] = c3;
            int hb = (t + 4) * CH + st;
            g_hist[hb] = c0; g_hist[hb + CH] = c1;
            g_hist[hb + 2 * CH] = c2; g_hist[hb + 3 * CH] = c3;
        }
        cur ^= 1;
    }

    // ---------------- tail frames (NF % 4; normally 0) ----------------
    for (int t = NFf; t < NF; t++) {
        float* Vc = cur ? V1 : V0;
        float* Vn = cur ? V0 : V1;
        __syncthreads();
        if (stOK) { float cv = Vc[my_pl]; candm[coff] = cv; g_hist[t * CH + st] = cv; }
        __syncthreads();
        float d0 = dens[3 * t], d1 = dens[3 * t + 1], d2 = dens[3 * t + 2];
        #pragma unroll
        for (int g = 0; g < 8; g++) {
            int idx = dw0 + (g << 7) + dL4;
            float4 A = *(const float4*)(Vc + idx);
            float pm = Vc[idx - 1];
            float4 o; o.x = pm + d0; o.y = A.x + d0; o.z = A.y + d0; o.w = A.z + d0;
            *(float4*)(Vn + idx) = o;
        }
        float acc = SENT;
        if (!skip) {
            const float4* c4 = (const float4*)candm + cb4;
            #pragma unroll
            for (int q = 0; q < 5; q++) {
                float4 cv = c4[q];
                acc = fmaxf(acc, cv.x + ltreg[4 * q + 0]);
                acc = fmaxf(acc, cv.y + ltreg[4 * q + 1]);
                acc = fmaxf(acc, cv.z + ltreg[4 * q + 2]);
                acc = fmaxf(acc, cv.w + ltreg[4 * q + 3]);
            }
        }
        float oth = __shfl_down_sync(0xffffffffu, acc, 1);
        __syncthreads();
        if (isA && cpart == 0) Vn[a_faddr] = fmaxf(acc, oth) + (a_fc == 2 ? d2 : d1);
        for (int k = 0; k < 32; k++) {
            int s = (tid << 5) + k;
            if (s < S) {
                int c = __ldg(pointer + s);
                if (c != 0 && !((fmask[s >> 5] >> (s & 31)) & 1u))
                    Vn[s] = Vc[s - 1] + (c == 2 ? d2 : d1);
            }
        }
        cur ^= 1;
    }
    __syncthreads();

    // ---------------- final argmax + backtrace ----------------
    float* Vf = cur ? V1 : V0;
    float* Vd = cur ? V0 : V1;
    float* rv = dens;
    int*   ri = (int*)(dens + NTH);
    int*   fof = (int*)Vd;
    if (isA && cpart == 0) fof[a_faddr] = task;
    {
        float bv = SENT; int bi = 0;
        #pragma unroll
        for (int k = 0; k < CAPV / NTH; k++) {
            int s = tid * (CAPV / NTH) + k;
            if (s < S) { float x = Vf[s]; if (x > bv) { bv = x; bi = s; } }
        }
        rv[tid] = bv; ri[tid] = bi;
    }
    __syncthreads();

    if (wid == 0) {
        float bv = SENT; int bi = 0x7fffffff;
        for (int m = lane; m < NTH; m += 32) {
            float x = rv[m]; int ii = ri[m];
            if (x > bv || (x == bv && ii < bi)) { bv = x; bi = ii; }
        }
        #pragma unroll
        for (int off = 16; off; off >>= 1) {
            float xv = __shfl_down_sync(0xffffffffu, bv, off);
            int   xi = __shfl_down_sync(0xffffffffu, bi, off);
            if (xv > bv || (xv == bv && xi < bi)) { bv = xv; bi = xi; }
        }
        bi = __shfl_sync(0xffffffffu, bi, 0);
        bv = __shfl_sync(0xffffffffu, bv, 0);
        if (lane == 0) {
            if (out_size > NF) out[NF] = bv;   // logp
            out[NF - 1] = (float)bi;           // path[NF-1]
        }

        int s = bi, tt = NF - 1;
        while (tt > 0) {
            bool isf = (fmask[s >> 5] >> (s & 31)) & 1u;
            if (isf) {
                int f = fof[s];
                int b = f / T, j = f - b * T;
                float bvv = SENT; int bii = 0x7fffffff;
                for (int i = lane; i < T; i += 32) {
                    float x = g_hist[tt * CH + b * T + i] + lt[i * T + j];
                    if (x > bvv || (x == bvv && i < bii)) { bvv = x; bii = i; }
                }
                #pragma unroll
                for (int off = 16; off; off >>= 1) {
                    float xv = __shfl_down_sync(0xffffffffu, bvv, off);
                    int   xi = __shfl_down_sync(0xffffffffu, bii, off);
                    if (xv > bvv || (xv == bvv && xi < bii)) { bvv = xv; bii = xi; }
                }
                bii = __shfl_sync(0xffffffffu, bii, 0);
                int p = plsm[b * T + bii];
                if (lane == 0) out[tt - 1] = (float)p;
                s = p; tt -= 1;
            } else {
                int ss = s - 1 - lane;
                bool ef = (ss < 0) ? true : (((fmask[ss >> 5] >> (ss & 31)) & 1u) != 0);
                unsigned flags = __ballot_sync(0xffffffffu, ef);
                int cnt2 = flags ? __ffs(flags) : 32;
                cnt2 = min(cnt2, tt);
                if (lane < cnt2) out[tt - 1 - lane] = (float)(s - 1 - lane);
                s -= cnt2; tt -= cnt2;
            }
        }
    }
}

extern "C" void kernel_launch(void* const* d_in, const int* in_sizes, int n_in,
                              void* d_out, int out_size)
{
    const float* acts = (const float*)d_in[0];
    const float* ltg  = (const float*)d_in[1];
    const int*   pl   = (const int*)d_in[2];
    const int*   fs   = (const int*)d_in[3];
    const int*   ptr  = (const int*)d_in[4];

    int NF = in_sizes[0] / 2;
    int T  = in_sizes[2] / 4;
    int S  = in_sizes[4];
    if (NF > NFMAX) NF = NFMAX;

    size_t smem = (size_t)SM_FLOATS * sizeof(float);
    static bool attr_set = false;
    if (!attr_set) {
        cudaFuncSetAttribute(dbn_kernel,
                             cudaFuncAttributeMaxDynamicSharedMemorySize, (int)smem);
        attr_set = true;
    }
    dbn_kernel<<<1, NTH, smem>>>(acts, ltg, pl, fs, ptr,
                                 (float*)d_out, S, T, NF, out_size);
}

// round 17
// speedup vs baseline: 1.4205x; 1.0054x over previous
#include <cuda_runtime.h>

#define NTH   512
#define CAPV  16384
#define CH    256
#define ENT   4
#define ELCAP 2048
#define SENT  (-1e38f)
#define NEGV  (-1e30f)
#define NFMAX 6000

// shared-memory float offsets
#define OFF_RAW0  0              // 16392: guard [0..3], V0 = +4
#define OFF_RAW1  16392          // 16392: guard [0..3], V1 = +4
#define OFF_LT    32784          // 4096
#define OFF_DENS  36880          // 18000: densq stride-12 per step (rv/ri overlay at end)
#define OFF_CANDM 54880          // 4*256: cand_m at m*256 + b*64 + i
#define OFF_TBUF  55904          // 4*256: T at task*4 + m  (16B-aligned)
#define OFF_PLSM  56928          // 256
#define OFF_FMASK 57184          // 512 uints (first-state bitmask)
#define OFF_MISC  57696          // 96: [0]=tot, [8..23]=wtot, [32..95]=band
#define SM_FLOATS 57792          // 231,168 B

__device__ float g_hist[NFMAX * CH];   // v_t[prev_last] history for backtrace

typedef unsigned long long u64;
__device__ __forceinline__ u64 pk2(float a, float b) {
    u64 r; asm("mov.b64 %0,{%1,%2};" : "=l"(r) : "f"(a), "f"(b)); return r;
}
__device__ __forceinline__ void upk2(u64 p, float& a, float& b) {
    asm("mov.b64 {%0,%1},%2;" : "=f"(a), "=f"(b) : "l"(p));
}
__device__ __forceinline__ u64 padd2(u64 a, u64 b) {
    u64 r; asm("add.rn.f32x2 %0, %1, %2;" : "=l"(r) : "l"(a), "l"(b)); return r;
}

// classify state s for the fused-4 update. Returns 1 + meta/start if exceptional.
__device__ __forceinline__ int classify(int s, const int* __restrict__ ptr,
                                        const unsigned* fmask, const int* fof0,
                                        int* meta, int* start)
{
    int r = -1;
    #pragma unroll
    for (int k = 0; k < 4; k++) {
        int x = s - k;
        if (r < 0 && x >= 0 && ((fmask[x >> 5] >> (x & 31)) & 1u)) r = k;
    }
    if (r >= 0) {   // within 3 of a first state f = s-r
        int f = s - r, j = fof0[f], m0 = 3 - r;
        unsigned codes = 0;
        #pragma unroll
        for (int m = 0; m < 4; m++) {
            unsigned c = (m < m0) ? 3u : (unsigned)__ldg(ptr + (f + (m - m0)));
            codes |= c << (2 * m);
        }
        *meta  = s | (1 << 14) | ((int)codes << 16);
        *start = j * 4 + m0;             // Tbuf index: task*4 + m0
        return 1;
    }
    unsigned codes = 0; int nz = 0;
    #pragma unroll
    for (int m = 0; m < 4; m++) {
        unsigned c = (unsigned)__ldg(ptr + (s - 3 + m));
        codes |= c << (2 * m);
        nz |= (c != 0u);
    }
    if (!nz) return 0;                   // clean dense state
    *meta  = s | ((int)codes << 16);
    *start = s - 4;                      // Vc index
    return 1;
}

__global__ void __launch_bounds__(NTH, 1)
dbn_kernel(const float* __restrict__ acts,
           const float* __restrict__ log_trans,
           const int*   __restrict__ prev_last,
           const int*   __restrict__ first_states,
           const int*   __restrict__ pointer,
           float*       __restrict__ out,
           int S, int T, int NF, int out_size)
{
    extern __shared__ float smf[];
    float* V0    = smf + OFF_RAW0 + 4;
    float* V1    = smf + OFF_RAW1 + 4;
    float* lt    = smf + OFF_LT;
    float* densq = smf + OFF_DENS;
    float* candm = smf + OFF_CANDM;
    float* Tsm   = smf + OFF_TBUF;
    int*   plsm  = (int*)(smf + OFF_PLSM);
    unsigned* fmask = (unsigned*)(smf + OFF_FMASK);
    int*   misc  = (int*)(smf + OFF_MISC);
    int*   band  = misc + 32;

    const int tid  = threadIdx.x;
    const int lane = tid & 31;
    const int wid  = tid >> 5;
    const int NT4  = 4 * T;

    // live dense blocks: only states < S matter. 113 blocks of 128 for S=14344.
    const int NBLK = (S + 127) >> 7;              // ceil(S/128)
    const int nb_lo = NBLK >> 4;                  // blocks for warps 0..14
    const int my_nb = (wid < 15) ? nb_lo : (NBLK - 15 * nb_lo);
    const int my_b0 = (wid < 15) ? wid * nb_lo : 15 * nb_lo;

    // ---------------- setup: tables ----------------
    for (int i = tid; i < T * T; i += NTH) lt[i] = log_trans[i];
    if (tid < NT4) plsm[tid] = prev_last[tid];
    for (int i = tid; i < 512; i += NTH) fmask[i] = 0u;
    for (int i = tid; i < 1024; i += NTH) candm[i] = 0.f;   // pads stay 0
    __syncthreads();

    int* fof0 = (int*)(smf + OFF_RAW0);      // setup overlay on V0 region
    if (tid < NT4) {
        int fs = first_states[tid];
        atomicOr(&fmask[fs >> 5], 1u << (fs & 31));
        fof0[fs] = tid;
    }
    __syncthreads();

    // ---------------- setup: exception entries (deterministic scan) ----------------
    int cnt = 0;
    for (int k = 0; k < 32; k++) {
        int s = (tid << 5) + k;
        if (s < S) { int mt, stx; cnt += classify(s, pointer, fmask, fof0, &mt, &stx); }
    }
    int inc = cnt;
    #pragma unroll
    for (int off = 1; off < 32; off <<= 1) {
        int n = __shfl_up_sync(0xffffffffu, inc, off);
        if (lane >= off) inc += n;
    }
    int* wtot = misc + 8;
    if (lane == 31) wtot[wid] = inc;
    __syncthreads();
    if (tid == 0) {
        int acc = 0;
        for (int w = 0; w < 16; w++) { int tw = wtot[w]; wtot[w] = acc; acc += tw; }
        misc[0] = acc;
    }
    __syncthreads();
    int base = wtot[wid] + inc - cnt;
    int* ex = (int*)(smf + OFF_RAW1);        // setup overlay on V1 region
    int* ey = ex + ELCAP;
    for (int k = 0; k < 32; k++) {
        int s = (tid << 5) + k;
        if (s < S) {
            int mt, stx;
            if (classify(s, pointer, fmask, fof0, &mt, &stx)) {
                if (base < ELCAP) { ex[base] = mt; ey[base] = stx; }
                base++;
            }
        }
    }
    // band per column j: contiguous finite range of lt[:,j] (≤ ~33 wide).
    // 40-wide aligned window [lo4, lo4+40) provably covers it and stays
    // inside the 64-float cand row (lo4 <= 24).
    if (tid < T) {
        int lo = 0;
        for (int i = 0; i < T; i++) if (lt[i * T + tid] > -1e28f) { lo = i; break; }
        int lo4 = lo & ~3;
        if (lo4 > 24) lo4 = 24;
        band[tid] = lo4;
    }
    __syncthreads();
    int nent = min(misc[0], ELCAP);
    int ems[ENT], eys[ENT];
    {
        int eb = (NTH - 1 - tid) * ENT;      // contiguous chunks, high tids first
        #pragma unroll
        for (int e = 0; e < ENT; e++) {
            int ix = eb + e;
            if (ix >= 0 && ix < nent) { ems[e] = ex[ix]; eys[e] = ey[ix]; }
            else                       { ems[e] = -1;     eys[e] = 0; }
        }
    }
    __syncthreads();                         // overlays dead; V0/V1 free

    // ---------------- setup: V0, guards, densities (stride-12 step layout) ----------------
    {
        float v0i = -logf((float)S);
        for (int s = tid; s < CAPV; s += NTH) V0[s] = v0i;
        if (tid < 4) { smf[OFF_RAW0 + tid] = NEGV; smf[OFF_RAW1 + tid] = NEGV; }
        for (int f = tid; f < NF; f += NTH) {
            int k = f >> 2, m = f & 3;
            float ab = acts[2 * f], ad = acts[2 * f + 1];
            densq[12 * k + m]     = logf((1.f - ab - ad) * (1.f / 15.f));
            densq[12 * k + 4 + m] = logf(ab);
            densq[12 * k + 8 + m] = logf(ad);
        }
    }

    // transition roles: 2 threads per task; 40-wide band, interleaved cpart blocks
    const bool isA  = (tid < 2 * NT4);
    const int  task  = tid >> 1;
    const int  cpart = tid & 1;
    int a_b = 0, a_faddr = 0, a_fc = 1;
    if (isA) {
        a_b = task / T;
        a_faddr = __ldg(first_states + task);
        a_fc = __ldg(pointer + a_faddr);     // 2 for beat0, else 1
    }
    __syncthreads();                         // lt/band ready; V0/densq ready

    float ltreg[20];
    int cb4 = 0;
    const bool skip = !isA;
    if (isA) {
        int a_j = task - a_b * T;
        int lo4 = band[a_j];
        cb4 = (a_b << 4) + (lo4 >> 2);       // window base in float4 units
        #pragma unroll
        for (int q = 0; q < 5; q++)
            #pragma unroll
            for (int e = 0; e < 4; e++) {
                int i = lo4 + ((q << 1) + cpart) * 4 + e;   // interleaved blocks
                ltreg[4 * q + e] = (i < T) ? lt[i * T + a_j] : SENT;
            }
    } else {
        #pragma unroll
        for (int q = 0; q < 20; q++) ltreg[q] = SENT;
    }

    // staging role: tid in [256, 256+NT4)
    const int st = tid - 256;
    const bool stOK = (st >= 0 && st < NT4);
    int my_pl = 0, coff = 0;
    if (stOK) { my_pl = plsm[st]; int b = st / T; coff = (b << 6) + (st - b * T); }

    const int dw0 = wid << 10;
    const int dL4 = lane << 2;

    int rem = NF & 3;
    int NFf = NF - rem;

    // pre-stage cand_0..3 from V0 (frames 0..3)
    if (NFf > 0 && stOK) {
        float e0 = densq[0], e1 = densq[1], e2 = densq[2];
        float c0 = V0[my_pl];
        float c1 = V0[my_pl - 1] + e0;
        float c2 = (V0[my_pl - 2] + e0) + e1;
        float c3 = ((V0[my_pl - 3] + e0) + e1) + e2;
        candm[coff] = c0; candm[256 + coff] = c1;
        candm[512 + coff] = c2; candm[768 + coff] = c3;
        g_hist[0 * CH + st] = c0; g_hist[1 * CH + st] = c1;
        g_hist[2 * CH + st] = c2; g_hist[3 * CH + st] = c3;
    }

    int cur = 0;

    // ---------------- fused-4 forward loop: 2 barriers / 4 frames ----------------
    for (int t = 0; t < NFf; t += 4) {
        float* Vc = cur ? V1 : V0;
        float* Vn = cur ? V0 : V1;
        __syncthreads();   // cand staged + exceptions applied to Vc

        const float* db = densq + 3 * t;     // 12*(t/4)
        float4 F0 = *(const float4*)(db);
        float4 F1 = *(const float4*)(db + 4);
        float4 F2 = *(const float4*)(db + 8);
        float dd[4][3];
        dd[0][0]=F0.x; dd[0][1]=F1.x; dd[0][2]=F2.x;
        dd[1][0]=F0.y; dd[1][1]=F1.y; dd[1][2]=F2.y;
        dd[2][0]=F0.z; dd[2][1]=F1.z; dd[2][2]=F2.z;
        dd[3][0]=F0.w; dd[3][1]=F1.w; dd[3][2]=F2.w;
        u64 D0 = pk2(F0.x, F0.x);
        u64 D1 = pk2(F0.y, F0.y);
        u64 D2 = pk2(F0.z, F0.z);
        u64 D3 = pk2(F0.w, F0.w);

        // dense: v_{t+4}[s] = v_t[s-4] + d0 chain, packed f32x2.
        for (int g = 0; g < my_nb; g++) {
            int idx = ((my_b0 + g) << 7) + dL4;
            float4 A = *(const float4*)(Vc + idx - 4);
            u64 p0 = pk2(A.x, A.y), p1 = pk2(A.z, A.w);
            p0 = padd2(p0, D0); p1 = padd2(p1, D0);
            p0 = padd2(p0, D1); p1 = padd2(p1, D1);
            p0 = padd2(p0, D2); p1 = padd2(p1, D2);
            p0 = padd2(p0, D3); p1 = padd2(p1, D3);
            float4 o; upk2(p0, o.x, o.y); upk2(p1, o.z, o.w);
            *(float4*)(Vn + idx) = o;
        }

        // transitions: T[task*4+m] = max_i cand_m[i] + lt[i][j], interleaved blocks
        float tm[4];
        #pragma unroll
        for (int m = 0; m < 4; m++) {
            float am = SENT;
            if (!skip) {
                const float4* c4 = (const float4*)(candm + (m << 8)) + cb4;
                float a0 = SENT, a1 = SENT, a2 = SENT, a3 = SENT;
                #pragma unroll
                for (int q = 0; q < 5; q++) {
                    float4 cv = c4[(q << 1) + cpart];
                    a0 = fmaxf(a0, cv.x + ltreg[4 * q + 0]);
                    a1 = fmaxf(a1, cv.y + ltreg[4 * q + 1]);
                    a2 = fmaxf(a2, cv.z + ltreg[4 * q + 2]);
                    a3 = fmaxf(a3, cv.w + ltreg[4 * q + 3]);
                }
                am = fmaxf(fmaxf(a0, a1), fmaxf(a2, a3));
            }
            float o = __shfl_down_sync(0xffffffffu, am, 1);
            tm[m] = fmaxf(am, o);
        }
        if (isA && cpart == 0) {
            float4 tv; tv.x = tm[0]; tv.y = tm[1]; tv.z = tm[2]; tv.w = tm[3];
            *(float4*)(Tsm + task * 4) = tv;
        }

        __syncthreads();   // Tbuf + dense Vn visible

        // exceptions: unified start + 4 slot-coded density adds
        #pragma unroll
        for (int e = 0; e < ENT; e++) {
            int me = ems[e];
            if (me >= 0) {
                int s = me & 0x3FFF;
                int kindA = (me >> 14) & 1;
                unsigned codes = ((unsigned)me) >> 16;
                float val = kindA ? Tsm[eys[e]] : Vc[eys[e]];
                #pragma unroll
                for (int m = 0; m < 4; m++) {
                    unsigned c = (codes >> (2 * m)) & 3u;
                    float add = (c == 0u) ? dd[m][0]
                              : (c == 1u) ? dd[m][1]
                              : (c == 2u) ? dd[m][2] : 0.f;
                    val += add;
                }
                Vn[s] = val;
            }
        }

        // stage next step's cand from Vn (pl slots are dense-written)
        if (stOK && t + 4 < NFf) {
            const float* db2 = densq + 3 * (t + 4);
            float e0 = db2[0], e1 = db2[1], e2 = db2[2];
            float c0 = Vn[my_pl];
            float c1 = Vn[my_pl - 1] + e0;
            float c2 = (Vn[my_pl - 2] + e0) + e1;
            float c3 = ((Vn[my_pl - 3] + e0) + e1) + e2;
            candm[coff] = c0; candm[256 + coff] = c1;
            candm[512 + coff] = c2; candm[768 + coff] = c3;
            int hb = (t + 4) * CH + st;
            g_hist[hb] = c0; g_hist[hb + CH] = c1;
            g_hist[hb + 2 * CH] = c2; g_hist[hb + 3 * CH] = c3;
        }
        cur ^= 1;
    }

    // ---------------- tail frames (NF % 4; normally 0) ----------------
    for (int t = NFf; t < NF; t++) {
        float* Vc = cur ? V1 : V0;
        float* Vn = cur ? V0 : V1;
        __syncthreads();
        if (stOK) { float cv = Vc[my_pl]; candm[coff] = cv; g_hist[t * CH + st] = cv; }
        __syncthreads();
        int tk = t >> 2, tmn = t & 3;
        float d0 = densq[12 * tk + tmn];
        float d1 = densq[12 * tk + 4 + tmn];
        float d2 = densq[12 * tk + 8 + tmn];
        #pragma unroll
        for (int g = 0; g < 8; g++) {
            int idx = dw0 + (g << 7) + dL4;
            float4 A = *(const float4*)(Vc + idx);
            float pm = Vc[idx - 1];
            float4 o; o.x = pm + d0; o.y = A.x + d0; o.z = A.y + d0; o.w = A.z + d0;
            *(float4*)(Vn + idx) = o;
        }
        float acc = SENT;
        if (!skip) {
            const float4* c4 = (const float4*)candm + cb4;
            #pragma unroll
            for (int q = 0; q < 5; q++) {
                float4 cv = c4[(q << 1) + cpart];
                acc = fmaxf(acc, cv.x + ltreg[4 * q + 0]);
                acc = fmaxf(acc, cv.y + ltreg[4 * q + 1]);
                acc = fmaxf(acc, cv.z + ltreg[4 * q + 2]);
                acc = fmaxf(acc, cv.w + ltreg[4 * q + 3]);
            }
        }
        float oth = __shfl_down_sync(0xffffffffu, acc, 1);
        __syncthreads();
        if (isA && cpart == 0) Vn[a_faddr] = fmaxf(acc, oth) + (a_fc == 2 ? d2 : d1);
        for (int k = 0; k < 32; k++) {
            int s = (tid << 5) + k;
            if (s < S) {
                int c = __ldg(pointer + s);
                if (c != 0 && !((fmask[s >> 5] >> (s & 31)) & 1u))
                    Vn[s] = Vc[s - 1] + (c == 2 ? d2 : d1);
            }
        }
        cur ^= 1;
    }
    __syncthreads();

    // ---------------- final argmax + backtrace ----------------
    float* Vf = cur ? V1 : V0;
    float* Vd = cur ? V0 : V1;
    float* rv = densq;                       // overlay (densities dead)
    int*   ri = (int*)(densq + NTH);
    int*   fof = (int*)Vd;
    if (isA && cpart == 0) fof[a_faddr] = task;
    {
        float bv = SENT; int bi = 0;
        #pragma unroll
        for (int k = 0; k < CAPV / NTH; k++) {
            int s = tid * (CAPV / NTH) + k;
            if (s < S) { float x = Vf[s]; if (x > bv) { bv = x; bi = s; } }
        }
        rv[tid] = bv; ri[tid] = bi;
    }
    __syncthreads();

    if (wid == 0) {
        float bv = SENT; int bi = 0x7fffffff;
        for (int m = lane; m < NTH; m += 32) {
            float x = rv[m]; int ii = ri[m];
            if (x > bv || (x == bv && ii < bi)) { bv = x; bi = ii; }
        }
        #pragma unroll
        for (int off = 16; off; off >>= 1) {
            float xv = __shfl_down_sync(0xffffffffu, bv, off);
            int   xi = __shfl_down_sync(0xffffffffu, bi, off);
            if (xv > bv || (xv == bv && xi < bi)) { bv = xv; bi = xi; }
        }
        bi = __shfl_sync(0xffffffffu, bi, 0);
        bv = __shfl_sync(0xffffffffu, bv, 0);
        if (lane == 0) {
            if (out_size > NF) out[NF] = bv;   // logp
            out[NF - 1] = (float)bi;           // path[NF-1]
        }

        int s = bi, tt = NF - 1;
        while (tt > 0) {
            bool isf = (fmask[s >> 5] >> (s & 31)) & 1u;
            if (isf) {
                int f = fof[s];
                int b = f / T, j = f - b * T;
                float bvv = SENT; int bii = 0x7fffffff;
                for (int i = lane; i < T; i += 32) {
                    float x = g_hist[tt * CH + b * T + i] + lt[i * T + j];
                    if (x > bvv || (x == bvv && i < bii)) { bvv = x; bii = i; }
                }
                #pragma unroll
                for (int off = 16; off; off >>= 1) {
                    float xv = __shfl_down_sync(0xffffffffu, bvv, off);
                    int   xi = __shfl_down_sync(0xffffffffu, bii, off);
                    if (xv > bvv || (xv == bvv && xi < bii)) { bvv = xv; bii = xi; }
                }
                bii = __shfl_sync(0xffffffffu, bii, 0);
                int p = plsm[b * T + bii];
                if (lane == 0) out[tt - 1] = (float)p;
                s = p; tt -= 1;
            } else {
                int ss = s - 1 - lane;
                bool ef = (ss < 0) ? true : (((fmask[ss >> 5] >> (ss & 31)) & 1u) != 0);
                unsigned flags = __ballot_sync(0xffffffffu, ef);
                int cnt2 = flags ? __ffs(flags) : 32;
                cnt2 = min(cnt2, tt);
                if (lane < cnt2) out[tt - 1 - lane] = (float)(s - 1 - lane);
                s -= cnt2; tt -= cnt2;
            }
        }
    }
}

extern "C" void kernel_launch(void* const* d_in, const int* in_sizes, int n_in,
                              void* d_out, int out_size)
{
    const float* acts = (const float*)d_in[0];
    const float* ltg  = (const float*)d_in[1];
    const int*   pl   = (const int*)d_in[2];
    const int*   fs   = (const int*)d_in[3];
    const int*   ptr  = (const int*)d_in[4];

    int NF = in_sizes[0] / 2;
    int T  = in_sizes[2] / 4;
    int S  = in_sizes[4];
    if (NF > NFMAX) NF = NFMAX;

    size_t smem = (size_t)SM_FLOATS * sizeof(float);
    static bool attr_set = false;
    if (!attr_set) {
        cudaFuncSetAttribute(dbn_kernel,
                             cudaFuncAttributeMaxDynamicSharedMemorySize, (int)smem);
        attr_set = true;
    }
    dbn_kernel<<<1, NTH, smem>>>(acts, ltg, pl, fs, ptr,
                                 (float*)d_out, S, T, NF, out_size);
}